// round 1
// baseline (speedup 1.0000x reference)
#include <cuda_runtime.h>
#include <cuda_bf16.h>
#include <math.h>

// Problem constants
#define VSZ 5000
#define HSZ 1024
#define ESZ 512
#define BSZ 64
#define TSZ 256
#define H4  (4 * HSZ)
#define MROWS (BSZ * TSZ)   // 16384

// ---------------- scratch (device globals; no allocation allowed) ----------
__device__ float g_x   [MROWS * ESZ];   // embedded input (B*T, E)      33.5 MB
__device__ float g_xg  [MROWS * H4];    // precomputed input gates       268 MB (reused for both layers)
__device__ float g_h1  [MROWS * HSZ];   // layer-1 hidden states          67 MB
__device__ float g_h2  [MROWS * HSZ];   // layer-2 hidden states          67 MB
__device__ float g_c   [BSZ * HSZ];     // cell state (reused per layer; t==0 implies 0)

// ---------------- embedding gather -----------------------------------------
__global__ void embed_kernel(const int* __restrict__ input,
                             const float* __restrict__ embed_W)
{
    int row = blockIdx.x;                 // b*T + t
    int idx = input[row];
    const float4* src = (const float4*)(embed_W + (size_t)idx * ESZ);
    float4* dst = (float4*)(g_x + (size_t)row * ESZ);
    dst[threadIdx.x] = src[threadIdx.x];  // 128 threads * float4 = 512 floats
}

// ---------------- generic SGEMM: C = A(MxK) * W(NxK)^T + b0 + b1 -----------
// BM=64, BN=64, BK=16, 256 threads, 4x4 microtile
__global__ void sgemm_bias(const float* __restrict__ A,
                           const float* __restrict__ W,
                           const float* __restrict__ b0,
                           const float* __restrict__ b1,
                           float* __restrict__ C,
                           int M, int N, int K)
{
    __shared__ float As[16][64];
    __shared__ float Ws[16][64];

    const int tid = threadIdx.x;
    const int ty = tid >> 4;          // 0..15
    const int tx = tid & 15;          // 0..15
    const int m0 = blockIdx.y * 64;
    const int n0 = blockIdx.x * 64;

    const int lr = tid >> 2;          // 0..63 (row within tile)
    const int lc = (tid & 3) << 2;    // 0,4,8,12 (k offset)

    float acc[4][4];
    #pragma unroll
    for (int i = 0; i < 4; i++)
        #pragma unroll
        for (int j = 0; j < 4; j++) acc[i][j] = 0.f;

    const int wrow = n0 + lr;
    const bool wok = (wrow < N);

    for (int k0 = 0; k0 < K; k0 += 16) {
        float4 av = *(const float4*)&A[(size_t)(m0 + lr) * K + k0 + lc];
        As[lc + 0][lr] = av.x; As[lc + 1][lr] = av.y;
        As[lc + 2][lr] = av.z; As[lc + 3][lr] = av.w;

        float4 wv = make_float4(0.f, 0.f, 0.f, 0.f);
        if (wok) wv = *(const float4*)&W[(size_t)wrow * K + k0 + lc];
        Ws[lc + 0][lr] = wv.x; Ws[lc + 1][lr] = wv.y;
        Ws[lc + 2][lr] = wv.z; Ws[lc + 3][lr] = wv.w;

        __syncthreads();

        #pragma unroll
        for (int k = 0; k < 16; k++) {
            float4 a = *(float4*)&As[k][ty << 2];
            float4 w = *(float4*)&Ws[k][tx << 2];
            acc[0][0] += a.x * w.x; acc[0][1] += a.x * w.y; acc[0][2] += a.x * w.z; acc[0][3] += a.x * w.w;
            acc[1][0] += a.y * w.x; acc[1][1] += a.y * w.y; acc[1][2] += a.y * w.z; acc[1][3] += a.y * w.w;
            acc[2][0] += a.z * w.x; acc[2][1] += a.z * w.y; acc[2][2] += a.z * w.z; acc[2][3] += a.z * w.w;
            acc[3][0] += a.w * w.x; acc[3][1] += a.w * w.y; acc[3][2] += a.w * w.z; acc[3][3] += a.w * w.w;
        }
        __syncthreads();
    }

    // epilogue
    float bias[4];
    #pragma unroll
    for (int j = 0; j < 4; j++) {
        int n = n0 + (tx << 2) + j;
        bias[j] = (n < N) ? (b0[n] + (b1 ? b1[n] : 0.f)) : 0.f;
    }
    #pragma unroll
    for (int i = 0; i < 4; i++) {
        int m = m0 + (ty << 2) + i;
        #pragma unroll
        for (int j = 0; j < 4; j++) {
            int n = n0 + (tx << 2) + j;
            if (n < N) C[(size_t)m * N + n] = acc[i][j] + bias[j];
        }
    }
}

// ---------------- fused LSTM step: gates GEMM + cell ------------------------
// One launch per timestep. Grid = 128 blocks (8 h-columns each), 256 threads.
// gates[b][g*H + h] = Xg[(b*T+t)*4H + g*H+h] + sum_k h_prev[b][k] * W_hh[g*H+h][k]
__global__ void lstm_step(const float* __restrict__ Xg,   // (B*T, 4H) with both biases baked in
                          const float* __restrict__ Whh,  // (4H, H)
                          float* h_all,                    // (B*T, H): read t-1, write t
                          float* c_st,                     // (B, H)
                          int t)
{
    __shared__ float Hs[16][64];   // h tile, k-major
    __shared__ float Ws[16][32];   // W tile, k-major
    __shared__ float Gs[64][32];   // staged gates

    const int tid = threadIdx.x;
    const int h0 = blockIdx.x * 8;
    const int ty = tid >> 4;          // 0..15 -> 4 rows each
    const int tx = tid & 15;          // 0..15 -> 2 cols each

    const int lr = tid >> 2;          // b row 0..63
    const int lc = (tid & 3) << 2;    // k offset

    float acc[4][2];
    #pragma unroll
    for (int i = 0; i < 4; i++) { acc[i][0] = 0.f; acc[i][1] = 0.f; }

    // W loader mapping (first 128 threads)
    int nl = tid >> 2;                            // 0..31 (only valid if tid<128)
    int wrow = ((nl >> 3) * HSZ) + h0 + (nl & 7); // gate*H + h

    for (int k0 = 0; k0 < HSZ; k0 += 16) {
        float4 hv = make_float4(0.f, 0.f, 0.f, 0.f);
        if (t > 0)
            hv = *(const float4*)&h_all[((size_t)lr * TSZ + (t - 1)) * HSZ + k0 + lc];
        Hs[lc + 0][lr] = hv.x; Hs[lc + 1][lr] = hv.y;
        Hs[lc + 2][lr] = hv.z; Hs[lc + 3][lr] = hv.w;

        if (tid < 128) {
            float4 wv = *(const float4*)&Whh[(size_t)wrow * HSZ + k0 + lc];
            Ws[lc + 0][nl] = wv.x; Ws[lc + 1][nl] = wv.y;
            Ws[lc + 2][nl] = wv.z; Ws[lc + 3][nl] = wv.w;
        }
        __syncthreads();

        #pragma unroll
        for (int k = 0; k < 16; k++) {
            float4 a = *(float4*)&Hs[k][ty << 2];
            float2 w = *(float2*)&Ws[k][tx << 1];
            acc[0][0] += a.x * w.x; acc[0][1] += a.x * w.y;
            acc[1][0] += a.y * w.x; acc[1][1] += a.y * w.y;
            acc[2][0] += a.z * w.x; acc[2][1] += a.z * w.y;
            acc[3][0] += a.w * w.x; acc[3][1] += a.w * w.y;
        }
        __syncthreads();
    }

    // add precomputed input gates, stage to shared
    #pragma unroll
    for (int i = 0; i < 4; i++) {
        int b = (ty << 2) + i;
        #pragma unroll
        for (int j = 0; j < 2; j++) {
            int nll = (tx << 1) + j;
            int n = ((nll >> 3) * HSZ) + h0 + (nll & 7);
            Gs[b][nll] = acc[i][j] + Xg[((size_t)b * TSZ + t) * H4 + n];
        }
    }
    __syncthreads();

    // cell update: 512 (b, j) elements, 2 per thread
    #pragma unroll
    for (int e = tid; e < 512; e += 256) {
        int b = e >> 3;
        int j = e & 7;
        float iv = Gs[b][j];
        float fv = Gs[b][8 + j];
        float gv = Gs[b][16 + j];
        float ov = Gs[b][24 + j];
        float cp = (t > 0) ? c_st[b * HSZ + h0 + j] : 0.f;
        float si = 1.f / (1.f + expf(-iv));
        float sf = 1.f / (1.f + expf(-fv));
        float so = 1.f / (1.f + expf(-ov));
        float cn = sf * cp + si * tanhf(gv);
        float hn = so * tanhf(cn);
        c_st[b * HSZ + h0 + j] = cn;
        h_all[((size_t)b * TSZ + t) * HSZ + h0 + j] = hn;
    }
}

// ---------------- launch ----------------------------------------------------
extern "C" void kernel_launch(void* const* d_in, const int* in_sizes, int n_in,
                              void* d_out, int out_size)
{
    const int*   input  = (const int*)  d_in[0];
    // d_in[1] = future (0), unused
    const float* embedW = (const float*)d_in[2];
    const float* W_ih1  = (const float*)d_in[3];
    const float* W_hh1  = (const float*)d_in[4];
    const float* b_ih1  = (const float*)d_in[5];
    const float* b_hh1  = (const float*)d_in[6];
    const float* W_ih2  = (const float*)d_in[7];
    const float* W_hh2  = (const float*)d_in[8];
    const float* b_ih2  = (const float*)d_in[9];
    const float* b_hh2  = (const float*)d_in[10];
    const float* lin_W  = (const float*)d_in[11];
    const float* lin_b  = (const float*)d_in[12];
    float* out = (float*)d_out;

    float *x, *xg, *h1, *h2, *c;
    cudaGetSymbolAddress((void**)&x,  g_x);
    cudaGetSymbolAddress((void**)&xg, g_xg);
    cudaGetSymbolAddress((void**)&h1, g_h1);
    cudaGetSymbolAddress((void**)&h2, g_h2);
    cudaGetSymbolAddress((void**)&c,  g_c);

    // 1. embed
    embed_kernel<<<MROWS, 128>>>(input, embedW);

    // 2. Xg1 = x @ W_ih1^T + b_ih1 + b_hh1
    {
        dim3 grid(H4 / 64, MROWS / 64);
        sgemm_bias<<<grid, 256>>>(x, W_ih1, b_ih1, b_hh1, xg, MROWS, H4, ESZ);
    }

    // 3. layer-1 recurrence
    for (int t = 0; t < TSZ; t++)
        lstm_step<<<HSZ / 8, 256>>>(xg, W_hh1, h1, c, t);

    // 4. Xg2 = h1 @ W_ih2^T + b_ih2 + b_hh2
    {
        dim3 grid(H4 / 64, MROWS / 64);
        sgemm_bias<<<grid, 256>>>(h1, W_ih2, b_ih2, b_hh2, xg, MROWS, H4, HSZ);
    }

    // 5. layer-2 recurrence
    for (int t = 0; t < TSZ; t++)
        lstm_step<<<HSZ / 8, 256>>>(xg, W_hh2, h2, c, t);

    // 6. outs = h2 @ lin_W^T + lin_b   -> directly into d_out (B, T, V)
    {
        dim3 grid((VSZ + 63) / 64, MROWS / 64);
        sgemm_bias<<<grid, 256>>>(h2, lin_W, lin_b, nullptr, out, MROWS, VSZ, HSZ);
    }
}

// round 2
// speedup vs baseline: 2.5762x; 2.5762x over previous
#include <cuda_runtime.h>
#include <math.h>

#define VSZ 5000
#define HSZ 1024
#define ESZ 512
#define BSZ 64
#define TSZ 256
#define H4  (4 * HSZ)
#define MROWS (BSZ * TSZ)   // 16384

// ---------------- scratch ---------------------------------------------------
__device__ float g_x [(size_t)MROWS * ESZ];
__device__ float g_xg[(size_t)MROWS * H4];
__device__ float g_h1[(size_t)MROWS * HSZ];
__device__ float g_h2[(size_t)MROWS * HSZ];
__device__ float g_c [BSZ * HSZ];

// ---------------- tf32 helpers ---------------------------------------------
__device__ __forceinline__ unsigned f2tf(float x) {
    unsigned u; asm("cvt.rna.tf32.f32 %0, %1;" : "=r"(u) : "f"(x)); return u;
}
__device__ __forceinline__ void mma8(float* c, const unsigned* a, const unsigned* b) {
    asm volatile(
        "mma.sync.aligned.m16n8k8.row.col.f32.tf32.tf32.f32 "
        "{%0,%1,%2,%3}, {%4,%5,%6,%7}, {%8,%9}, {%0,%1,%2,%3};\n"
        : "+f"(c[0]), "+f"(c[1]), "+f"(c[2]), "+f"(c[3])
        : "r"(a[0]), "r"(a[1]), "r"(a[2]), "r"(a[3]), "r"(b[0]), "r"(b[1]));
}

// ---------------- embedding gather -----------------------------------------
__global__ void embed_kernel(const int* __restrict__ input,
                             const float* __restrict__ embed_W)
{
    int row = blockIdx.x;
    int idx = input[row];
    const float4* src = (const float4*)(embed_W + (size_t)idx * ESZ);
    float4* dst = (float4*)(g_x + (size_t)row * ESZ);
    dst[threadIdx.x] = src[threadIdx.x];
}

// ---------------- tf32 tensor GEMM: C = A(MxK) @ W(NxK)^T + b0 (+ b1) ------
// BM=128, BN=64, BK=16, 256 threads (8 warps as 4m x 2n, warp tile 32x32)
#define KP 20   // padded k-stride (16 + 4): conflict-free fragment loads

__global__ void __launch_bounds__(256, 2)
tgemm(const float* __restrict__ A, const float* __restrict__ W,
      const float* __restrict__ b0v, const float* __restrict__ b1v,
      float* __restrict__ C, int M, int N, int K)
{
    __shared__ unsigned As[2][128][KP];
    __shared__ unsigned Ws[2][64][KP];

    const int tid = threadIdx.x, lane = tid & 31, wid = tid >> 5;
    const int m0 = blockIdx.y * 128, n0 = blockIdx.x * 64;
    const int wm = (wid >> 1) * 32, wn = (wid & 1) * 32;
    const int r = lane >> 2, q = lane & 3;

    float acc[2][4][4];
    #pragma unroll
    for (int i = 0; i < 2; i++)
        #pragma unroll
        for (int j = 0; j < 4; j++)
            #pragma unroll
            for (int k = 0; k < 4; k++) acc[i][j][k] = 0.f;

    const int NIT = K / 16;

    // staging register carriers
    float4 aR[2]; float4 bR;
    const int arow0 = tid >> 2;            // 0..63  (A rows, part 0)
    const int akg   = (tid & 3) * 4;       // k offset
    const int bnl   = tid >> 2;            // 0..63  (W rows)
    const int wrow  = n0 + bnl;
    const bool wok  = (wrow < N);

    // prologue: load + stage tile 0
    {
        aR[0] = *(const float4*)&A[(size_t)(m0 + arow0) * K + akg];
        aR[1] = *(const float4*)&A[(size_t)(m0 + 64 + arow0) * K + akg];
        bR = wok ? *(const float4*)&W[(size_t)wrow * K + akg] : make_float4(0,0,0,0);
        unsigned* s0 = &As[0][arow0][akg];
        s0[0]=f2tf(aR[0].x); s0[1]=f2tf(aR[0].y); s0[2]=f2tf(aR[0].z); s0[3]=f2tf(aR[0].w);
        unsigned* s1 = &As[0][64 + arow0][akg];
        s1[0]=f2tf(aR[1].x); s1[1]=f2tf(aR[1].y); s1[2]=f2tf(aR[1].z); s1[3]=f2tf(aR[1].w);
        unsigned* sw = &Ws[0][bnl][akg];
        sw[0]=f2tf(bR.x); sw[1]=f2tf(bR.y); sw[2]=f2tf(bR.z); sw[3]=f2tf(bR.w);
    }
    __syncthreads();

    for (int it = 0; it < NIT; ++it) {
        if (it + 1 < NIT) {
            int k0 = (it + 1) * 16;
            aR[0] = *(const float4*)&A[(size_t)(m0 + arow0) * K + k0 + akg];
            aR[1] = *(const float4*)&A[(size_t)(m0 + 64 + arow0) * K + k0 + akg];
            bR = wok ? *(const float4*)&W[(size_t)wrow * K + k0 + akg] : make_float4(0,0,0,0);
        }
        const int bf = it & 1;
        #pragma unroll
        for (int kc = 0; kc < 16; kc += 8) {
            unsigned af[2][4];
            #pragma unroll
            for (int tm = 0; tm < 2; tm++) {
                af[tm][0] = As[bf][wm + tm*16 + r    ][kc + q];
                af[tm][1] = As[bf][wm + tm*16 + r + 8][kc + q];
                af[tm][2] = As[bf][wm + tm*16 + r    ][kc + q + 4];
                af[tm][3] = As[bf][wm + tm*16 + r + 8][kc + q + 4];
            }
            unsigned bg[4][2];
            #pragma unroll
            for (int tn = 0; tn < 4; tn++) {
                bg[tn][0] = Ws[bf][wn + tn*8 + r][kc + q];
                bg[tn][1] = Ws[bf][wn + tn*8 + r][kc + q + 4];
            }
            #pragma unroll
            for (int tm = 0; tm < 2; tm++)
                #pragma unroll
                for (int tn = 0; tn < 4; tn++)
                    mma8(acc[tm][tn], af[tm], bg[tn]);
        }
        if (it + 1 < NIT) {
            const int nb = (it + 1) & 1;
            unsigned* s0 = &As[nb][arow0][akg];
            s0[0]=f2tf(aR[0].x); s0[1]=f2tf(aR[0].y); s0[2]=f2tf(aR[0].z); s0[3]=f2tf(aR[0].w);
            unsigned* s1 = &As[nb][64 + arow0][akg];
            s1[0]=f2tf(aR[1].x); s1[1]=f2tf(aR[1].y); s1[2]=f2tf(aR[1].z); s1[3]=f2tf(aR[1].w);
            unsigned* sw = &Ws[nb][bnl][akg];
            sw[0]=f2tf(bR.x); sw[1]=f2tf(bR.y); sw[2]=f2tf(bR.z); sw[3]=f2tf(bR.w);
        }
        __syncthreads();
    }

    // epilogue
    #pragma unroll
    for (int tm = 0; tm < 2; tm++) {
        #pragma unroll
        for (int tn = 0; tn < 4; tn++) {
            int n = n0 + wn + tn*8 + 2*q;
            float bb0 = 0.f, bb1 = 0.f;
            if (n < N)     bb0 = b0v[n]     + (b1v ? b1v[n]     : 0.f);
            if (n + 1 < N) bb1 = b0v[n + 1] + (b1v ? b1v[n + 1] : 0.f);
            int m = m0 + wm + tm*16 + r;
            if (n < N) {
                C[(size_t)m * N + n]       = acc[tm][tn][0] + bb0;
                C[(size_t)(m+8) * N + n]   = acc[tm][tn][2] + bb0;
            }
            if (n + 1 < N) {
                C[(size_t)m * N + n + 1]     = acc[tm][tn][1] + bb1;
                C[(size_t)(m+8) * N + n + 1] = acc[tm][tn][3] + bb1;
            }
        }
    }
}

// ---------------- fused LSTM step (tf32 tensor) -----------------------------
// Grid 128 blocks x 256 thr. Block: 8 h-cols x 4 gates = 32 gate cols, M=64.
// 8 warps: 4 m-tiles x 2 k-halves; warp tile 16x32, K-half = 512.
__global__ void __launch_bounds__(256, 1)
lstm_step_t(const float* __restrict__ Xg, const float* __restrict__ Whh,
            float* __restrict__ h_all, float* __restrict__ c_st, int t)
{
    __shared__ unsigned Hs[2][2][64][KP];   // [buf][half][m][k]
    __shared__ unsigned Ws2[2][2][32][KP];  // [buf][half][n][k]
    __shared__ float Gb[2][64][33];

    const int tid = threadIdx.x, lane = tid & 31, wid = tid >> 5;
    const int h0 = blockIdx.x * 8;
    const int mw = wid & 3, kh = wid >> 2;
    const int r = lane >> 2, q = lane & 3;

    float acc[4][4];
    #pragma unroll
    for (int i = 0; i < 4; i++)
        #pragma unroll
        for (int j = 0; j < 4; j++) acc[i][j] = 0.f;

    if (t > 0) {
        const int hrow = tid >> 2;          // 0..63
        const int kg   = (tid & 3) * 4;
        const int wh   = tid >> 7;          // 0/1: W half
        const int wnl  = (tid & 127) >> 2;  // 0..31
        const int wrow = ((wnl >> 3) * HSZ) + h0 + (wnl & 7);

        float4 hR[2]; float4 wR;
        const float* hbase = &h_all[((size_t)hrow * TSZ + (t - 1)) * HSZ];
        const float* wbase = &Whh[(size_t)wrow * HSZ + wh * 512];

        // prologue
        hR[0] = *(const float4*)&hbase[kg];
        hR[1] = *(const float4*)&hbase[512 + kg];
        wR    = *(const float4*)&wbase[kg];
        {
            unsigned* p0 = &Hs[0][0][hrow][kg];
            p0[0]=f2tf(hR[0].x); p0[1]=f2tf(hR[0].y); p0[2]=f2tf(hR[0].z); p0[3]=f2tf(hR[0].w);
            unsigned* p1 = &Hs[0][1][hrow][kg];
            p1[0]=f2tf(hR[1].x); p1[1]=f2tf(hR[1].y); p1[2]=f2tf(hR[1].z); p1[3]=f2tf(hR[1].w);
            unsigned* pw = &Ws2[0][wh][wnl][kg];
            pw[0]=f2tf(wR.x); pw[1]=f2tf(wR.y); pw[2]=f2tf(wR.z); pw[3]=f2tf(wR.w);
        }
        __syncthreads();

        for (int it = 0; it < 32; ++it) {
            if (it + 1 < 32) {
                int k0 = (it + 1) * 16;
                hR[0] = *(const float4*)&hbase[k0 + kg];
                hR[1] = *(const float4*)&hbase[512 + k0 + kg];
                wR    = *(const float4*)&wbase[k0 + kg];
            }
            const int bf = it & 1;
            #pragma unroll
            for (int kc = 0; kc < 16; kc += 8) {
                unsigned af[4];
                af[0] = Hs[bf][kh][mw*16 + r    ][kc + q];
                af[1] = Hs[bf][kh][mw*16 + r + 8][kc + q];
                af[2] = Hs[bf][kh][mw*16 + r    ][kc + q + 4];
                af[3] = Hs[bf][kh][mw*16 + r + 8][kc + q + 4];
                #pragma unroll
                for (int tn = 0; tn < 4; tn++) {
                    unsigned bg[2];
                    bg[0] = Ws2[bf][kh][tn*8 + r][kc + q];
                    bg[1] = Ws2[bf][kh][tn*8 + r][kc + q + 4];
                    mma8(acc[tn], af, bg);
                }
            }
            if (it + 1 < 32) {
                const int nb = (it + 1) & 1;
                int k0 = (it + 1) * 16; (void)k0;
                unsigned* p0 = &Hs[nb][0][hrow][kg];
                p0[0]=f2tf(hR[0].x); p0[1]=f2tf(hR[0].y); p0[2]=f2tf(hR[0].z); p0[3]=f2tf(hR[0].w);
                unsigned* p1 = &Hs[nb][1][hrow][kg];
                p1[0]=f2tf(hR[1].x); p1[1]=f2tf(hR[1].y); p1[2]=f2tf(hR[1].z); p1[3]=f2tf(hR[1].w);
                unsigned* pw = &Ws2[nb][wh][wnl][kg];
                pw[0]=f2tf(wR.x); pw[1]=f2tf(wR.y); pw[2]=f2tf(wR.z); pw[3]=f2tf(wR.w);
            }
            __syncthreads();
        }
    }

    // write accumulators for this k-half
    #pragma unroll
    for (int tn = 0; tn < 4; tn++) {
        int col = tn*8 + 2*q;
        Gb[kh][mw*16 + r    ][col]     = acc[tn][0];
        Gb[kh][mw*16 + r    ][col + 1] = acc[tn][1];
        Gb[kh][mw*16 + r + 8][col]     = acc[tn][2];
        Gb[kh][mw*16 + r + 8][col + 1] = acc[tn][3];
    }
    __syncthreads();

    // cell update: 512 (b, j) elems
    #pragma unroll
    for (int e = tid; e < 512; e += 256) {
        int b = e >> 3, j = e & 7;
        size_t base = ((size_t)b * TSZ + t) * H4;
        float iv = Gb[0][b][j]      + Gb[1][b][j]      + Xg[base + 0*HSZ + h0 + j];
        float fv = Gb[0][b][8 + j]  + Gb[1][b][8 + j]  + Xg[base + 1*HSZ + h0 + j];
        float gv = Gb[0][b][16 + j] + Gb[1][b][16 + j] + Xg[base + 2*HSZ + h0 + j];
        float ov = Gb[0][b][24 + j] + Gb[1][b][24 + j] + Xg[base + 3*HSZ + h0 + j];
        float cp = (t > 0) ? c_st[b * HSZ + h0 + j] : 0.f;
        float si = 1.f / (1.f + expf(-iv));
        float sf = 1.f / (1.f + expf(-fv));
        float so = 1.f / (1.f + expf(-ov));
        float cn = sf * cp + si * tanhf(gv);
        float hn = so * tanhf(cn);
        c_st[b * HSZ + h0 + j] = cn;
        h_all[((size_t)b * TSZ + t) * HSZ + h0 + j] = hn;
    }
}

// ---------------- launch ----------------------------------------------------
extern "C" void kernel_launch(void* const* d_in, const int* in_sizes, int n_in,
                              void* d_out, int out_size)
{
    const int*   input  = (const int*)  d_in[0];
    const float* embedW = (const float*)d_in[2];
    const float* W_ih1  = (const float*)d_in[3];
    const float* W_hh1  = (const float*)d_in[4];
    const float* b_ih1  = (const float*)d_in[5];
    const float* b_hh1  = (const float*)d_in[6];
    const float* W_ih2  = (const float*)d_in[7];
    const float* W_hh2  = (const float*)d_in[8];
    const float* b_ih2  = (const float*)d_in[9];
    const float* b_hh2  = (const float*)d_in[10];
    const float* lin_W  = (const float*)d_in[11];
    const float* lin_b  = (const float*)d_in[12];
    float* out = (float*)d_out;

    float *x, *xg, *h1, *h2, *c;
    cudaGetSymbolAddress((void**)&x,  g_x);
    cudaGetSymbolAddress((void**)&xg, g_xg);
    cudaGetSymbolAddress((void**)&h1, g_h1);
    cudaGetSymbolAddress((void**)&h2, g_h2);
    cudaGetSymbolAddress((void**)&c,  g_c);

    embed_kernel<<<MROWS, 128>>>(input, embedW);

    {   // Xg1 = x @ W_ih1^T + b_ih1 + b_hh1
        dim3 grid(H4 / 64, MROWS / 128);
        tgemm<<<grid, 256>>>(x, W_ih1, b_ih1, b_hh1, xg, MROWS, H4, ESZ);
    }
    for (int t = 0; t < TSZ; t++)
        lstm_step_t<<<HSZ / 8, 256>>>(xg, W_hh1, h1, c, t);

    {   // Xg2 = h1 @ W_ih2^T + b_ih2 + b_hh2
        dim3 grid(H4 / 64, MROWS / 128);
        tgemm<<<grid, 256>>>(h1, W_ih2, b_ih2, b_hh2, xg, MROWS, H4, HSZ);
    }
    for (int t = 0; t < TSZ; t++)
        lstm_step_t<<<HSZ / 8, 256>>>(xg, W_hh2, h2, c, t);

    {   // outs = h2 @ lin_W^T + lin_b
        dim3 grid((VSZ + 63) / 64, MROWS / 128);
        tgemm<<<grid, 256>>>(h2, lin_W, lin_b, nullptr, out, MROWS, VSZ, HSZ);
    }
}